// round 12
// baseline (speedup 1.0000x reference)
#include <cuda_runtime.h>
#include <cuda_bf16.h>
#include <cstdint>
#include <math.h>

#define S_DIM 128
#define U_DIM 128
#define H_DIM 512
#define V_DIM 8192
#define M_DIM (S_DIM * U_DIM)   /* 16384 */
#define K2_DIM (2 * H_DIM)      /* 1024  */

// ---------------- scratch (static device globals; no allocations) ----------
__device__ float g_xw[M_DIM * H_DIM];            // x_emb @ W_ih^T + biases
__device__ float g_out[M_DIM * H_DIM];           // RNN outputs
__device__ float g_w[U_DIM * S_DIM * S_DIM];     // flashback weights [u][i][j]
__device__ float g_sumw[U_DIM * S_DIM];
__device__ __nv_bfloat16 g_Ahi[(size_t)M_DIM * H_DIM];    // FC A hi (out_w only)
__device__ __nv_bfloat16 g_Alo[(size_t)M_DIM * H_DIM];    // FC A lo
__device__ __nv_bfloat16 g_Whi[(size_t)V_DIM * K2_DIM];   // FC W hi (full 1024)
__device__ __nv_bfloat16 g_Wlo[(size_t)V_DIM * K2_DIM];   // FC W lo
__device__ __nv_bfloat16 g_Xhi[(size_t)M_DIM * H_DIM];    // gathered x_emb hi
__device__ __nv_bfloat16 g_Xlo[(size_t)M_DIM * H_DIM];    // gathered x_emb lo
__device__ __nv_bfloat16 g_WihHi[H_DIM * H_DIM];
__device__ __nv_bfloat16 g_WihLo[H_DIM * H_DIM];
__device__ __nv_bfloat16 g_Phi[U_DIM * H_DIM];            // p_u hi
__device__ __nv_bfloat16 g_Plo[U_DIM * H_DIM];            // p_u lo
__device__ float g_P[(size_t)U_DIM * V_DIM];              // p_u @ W2^T + fc_b
__device__ float g_bias2[H_DIM];                          // b_ih + b_hh
__device__ unsigned g_bar_count;
__device__ unsigned g_bar_gen;

__device__ __forceinline__ uint32_t smem_u32(const void* p) {
  uint32_t a;
  asm("{ .reg .u64 t; cvta.to.shared.u64 t, %1; cvt.u32.u64 %0, t; }"
      : "=r"(a) : "l"(p));
  return a;
}
#define SMEM_SWIZZLE_128B(o) ((o) ^ (((o) >> 3) & 0x70))

// ---------------------------------------------------------------------------
// split helpers
// ---------------------------------------------------------------------------
__global__ __launch_bounds__(256) void wsplit(const float* __restrict__ w,
                                              __nv_bfloat16* __restrict__ hi,
                                              __nv_bfloat16* __restrict__ lo) {
  size_t i = ((size_t)blockIdx.x * 256 + threadIdx.x) * 4;
  float4 v = *(const float4*)(w + i);
  float vv[4] = {v.x, v.y, v.z, v.w};
#pragma unroll
  for (int j = 0; j < 4; j++) {
    __nv_bfloat16 h = __float2bfloat16(vv[j]);
    hi[i + j] = h;
    lo[i + j] = __float2bfloat16(vv[j] - __bfloat162float(h));
  }
}

__global__ __launch_bounds__(128) void gather_split(const int* __restrict__ x,
                                                    const float* __restrict__ emb) {
  const int m = blockIdx.x;
  const int tid = threadIdx.x;
  const int row = x[m];
  float4 v = *(const float4*)(emb + (size_t)row * H_DIM + tid * 4);
  float vv[4] = {v.x, v.y, v.z, v.w};
  size_t base = (size_t)m * H_DIM + tid * 4;
#pragma unroll
  for (int j = 0; j < 4; j++) {
    __nv_bfloat16 h = __float2bfloat16(vv[j]);
    g_Xhi[base + j] = h;
    g_Xlo[base + j] = __float2bfloat16(vv[j] - __bfloat162float(h));
  }
}

// gathers p_u, splits it, and (block 0) also builds b_ih+b_hh
__global__ __launch_bounds__(128) void pu_split(const int* __restrict__ au,
                                                const float* __restrict__ uemb,
                                                const float* __restrict__ bih,
                                                const float* __restrict__ bhh) {
  const int u = blockIdx.x;
  const int tid = threadIdx.x;
  if (u == 0) {
#pragma unroll
    for (int j = 0; j < 4; j++) {
      int i = tid * 4 + j;
      g_bias2[i] = bih[i] + bhh[i];
    }
  }
  float4 v = *(const float4*)(&uemb[(size_t)au[u] * H_DIM + tid * 4]);
  float vv[4] = {v.x, v.y, v.z, v.w};
  size_t base = (size_t)u * H_DIM + tid * 4;
#pragma unroll
  for (int j = 0; j < 4; j++) {
    __nv_bfloat16 h = __float2bfloat16(vv[j]);
    g_Phi[base + j] = h;
    g_Plo[base + j] = __float2bfloat16(vv[j] - __bfloat162float(h));
  }
}

// ---------------------------------------------------------------------------
// flashback weights + row sums (fast-math transcendentals)
// ---------------------------------------------------------------------------
__global__ __launch_bounds__(128) void flashweights(
    const float* __restrict__ t, const float* __restrict__ sc) {
  const int i = blockIdx.x, u = blockIdx.y;
  const int j = threadIdx.x;
  float w = 0.f;
  if (j <= i) {
    float ti = t[i * U_DIM + u], tj = t[j * U_DIM + u];
    float six = sc[(i * U_DIM + u) * 2 + 0], siy = sc[(i * U_DIM + u) * 2 + 1];
    float sjx = sc[(j * U_DIM + u) * 2 + 0], sjy = sc[(j * U_DIM + u) * 2 + 1];
    float dt = ti - tj;
    float dx = six - sjx, dy = siy - sjy;
    float ds = sqrtf(dx * dx + dy * dy);
    float a = (__cosf(dt * 7.2722052166430399e-05f) + 1.0f) * 0.5f *
              __expf(dt * (-0.1f / 86400.0f));
    float b = __expf(-100.0f * ds);
    w = a * b + 1e-10f;
  }
  g_w[((size_t)u * S_DIM + i) * S_DIM + j] = w;
  __shared__ float red[128];
  red[j] = w;
  __syncthreads();
#pragma unroll
  for (int st = 64; st > 0; st >>= 1) {
    if (j < st) red[j] += red[j + st];
    __syncthreads();
  }
  if (j == 0) g_sumw[u * S_DIM + i] = red[0];
}

// ---------------------------------------------------------------------------
// persistent RNN — R8 core; last step also writes h_out to the output tail
// ---------------------------------------------------------------------------
#define RNN_WS 34
#define RNN_HS 18
#define RNN_SMEM (512 * RNN_WS * 4 + 512 * RNN_HS * 4)
__global__ __launch_bounds__(128) void rnn_persist(const float* __restrict__ h_in,
                                                   const float* __restrict__ Whh,
                                                   float* __restrict__ hout_dst) {
  extern __shared__ float sf[];
  float* Ws = sf;
  float* Hs = sf + 512 * RNN_WS;
  const int tid = threadIdx.x;
  const int n0 = blockIdx.x * 32;
  const int u0base = blockIdx.y * 16;
  {
    int c = tid & 31, kg = tid >> 5;
    for (int k0 = 0; k0 < 512; k0 += 16) {
      int k = k0 + kg * 4;
      float4 v = *(const float4*)(Whh + (size_t)(n0 + c) * H_DIM + k);
      Ws[(k + 0) * RNN_WS + c] = v.x; Ws[(k + 1) * RNN_WS + c] = v.y;
      Ws[(k + 2) * RNN_WS + c] = v.z; Ws[(k + 3) * RNN_WS + c] = v.w;
    }
  }
  unsigned mygen = 0;
  if (tid == 0) mygen = *((volatile unsigned*)&g_bar_gen);
  __syncthreads();

  const int tx = tid & 15, ty = tid >> 4;
  for (int s = 0; s < S_DIM; s++) {
    const float* hp = (s == 0) ? h_in : (g_out + (size_t)(s - 1) * U_DIM * H_DIM);
    {
      int uu = tid >> 3, kg2 = tid & 7;
      const float* hrow = hp + (size_t)(u0base + uu) * H_DIM;
      for (int k0 = 0; k0 < 512; k0 += 32) {
        int k = k0 + kg2 * 4;
        float4 v = *(const float4*)(hrow + k);
        Hs[(k + 0) * RNN_HS + uu] = v.x; Hs[(k + 1) * RNN_HS + uu] = v.y;
        Hs[(k + 2) * RNN_HS + uu] = v.z; Hs[(k + 3) * RNN_HS + uu] = v.w;
      }
    }
    __syncthreads();
    float a00 = 0.f, a01 = 0.f, a10 = 0.f, a11 = 0.f;
#pragma unroll 8
    for (int k = 0; k < 512; k++) {
      float2 a = *(const float2*)(&Hs[k * RNN_HS + ty * 2]);
      float2 b = *(const float2*)(&Ws[k * RNN_WS + tx * 2]);
      a00 += a.x * b.x; a01 += a.x * b.y;
      a10 += a.y * b.x; a11 += a.y * b.y;
    }
    const float* xw = g_xw + (size_t)s * U_DIM * H_DIM;
    float* ho = g_out + (size_t)s * U_DIM * H_DIM;
    size_t o00 = (size_t)(u0base + ty * 2) * H_DIM + n0 + tx * 2;
    size_t o10 = o00 + H_DIM;
    float v00 = tanhf(a00 + xw[o00]);
    float v01 = tanhf(a01 + xw[o00 + 1]);
    float v10 = tanhf(a10 + xw[o10]);
    float v11 = tanhf(a11 + xw[o10 + 1]);
    ho[o00]     = v00;
    ho[o00 + 1] = v01;
    ho[o10]     = v10;
    ho[o10 + 1] = v11;
    if (s == S_DIM - 1) {
      hout_dst[o00]     = v00;
      hout_dst[o00 + 1] = v01;
      hout_dst[o10]     = v10;
      hout_dst[o10 + 1] = v11;
    }
    __syncthreads();
    if (tid == 0) {
      __threadfence();
      unsigned arr = atomicAdd(&g_bar_count, 1);
      if (arr == 127) {
        g_bar_count = 0;
        __threadfence();
        atomicAdd(&g_bar_gen, 1);
      } else {
        while (*((volatile unsigned*)&g_bar_gen) == mygen) { }
        __threadfence();
      }
      mygen++;
    }
    __syncthreads();
  }
}

// ---------------------------------------------------------------------------
// per-user einsum -> bf16 hi/lo of FC A (stride 512) — R8 exact
// ---------------------------------------------------------------------------
__global__ __launch_bounds__(128) void einsum_gemm() {
  __shared__ float As[16][32];
  __shared__ float Bs[16][64];
  const int nt = blockIdx.x, mt = blockIdx.y, u = blockIdx.z;
  const int tid = threadIdx.x;
  const int m0 = mt * 32, n0 = nt * 64;
  const int tx = tid & 15, ty = tid >> 4;
  float acc[4][4];
#pragma unroll
  for (int i = 0; i < 4; i++)
#pragma unroll
    for (int j = 0; j < 4; j++) acc[i][j] = 0.f;
  for (int k0 = 0; k0 < 128; k0 += 16) {
    {
      int row = tid >> 2, kq = (tid & 3) * 4;
      float4 v = *(const float4*)(&g_w[((size_t)u * S_DIM + m0 + row) * S_DIM + k0 + kq]);
      As[kq + 0][row] = v.x; As[kq + 1][row] = v.y;
      As[kq + 2][row] = v.z; As[kq + 3][row] = v.w;
    }
#pragma unroll
    for (int h2 = 0; h2 < 2; h2++) {
      int id = tid + h2 * 128;
      int jr = id >> 4, hq = (id & 15) * 4;
      float4 v = *(const float4*)(&g_out[((size_t)(k0 + jr) * U_DIM + u) * H_DIM + n0 + hq]);
      *(float4*)(&Bs[jr][hq]) = v;
    }
    __syncthreads();
#pragma unroll
    for (int k = 0; k < 16; k++) {
      float a[4], b[4];
      *(float4*)(&a[0]) = *(const float4*)(&As[k][ty * 4]);
      *(float4*)(&b[0]) = *(const float4*)(&Bs[k][tx * 4]);
#pragma unroll
      for (int i = 0; i < 4; i++)
#pragma unroll
        for (int j = 0; j < 4; j++) acc[i][j] += a[i] * b[j];
    }
    __syncthreads();
  }
#pragma unroll
  for (int r = 0; r < 4; r++) {
    int i = m0 + ty * 4 + r;
    float inv = 1.0f / g_sumw[u * S_DIM + i];
#pragma unroll
    for (int c = 0; c < 4; c++) {
      int h = n0 + tx * 4 + c;
      float v = acc[r][c] * inv;
      size_t idx = ((size_t)i * U_DIM + u) * H_DIM + h;
      __nv_bfloat16 hi = __float2bfloat16(v);
      g_Ahi[idx] = hi;
      g_Alo[idx] = __float2bfloat16(v - __bfloat162float(hi));
    }
  }
}

// ---------------------------------------------------------------------------
// 3-term bf16-split GEMM, fused-term stages (R11 exact — current best)
// ---------------------------------------------------------------------------
#define FCS_AHI 0
#define FCS_ALO 16384
#define FCS_BHI 32768
#define FCS_BLO 49152
#define FC_STAGE 65536
#define FC_BIAS_OFF 131072
#define FC_SMEM 131584
__global__ __launch_bounds__(256) void gemm3(
    const __nv_bfloat16* __restrict__ Ahi, const __nv_bfloat16* __restrict__ Alo,
    const __nv_bfloat16* __restrict__ Bhi, const __nv_bfloat16* __restrict__ Blo,
    const float* __restrict__ bias, const float* __restrict__ P,
    float* __restrict__ C, int lda, int ldb, int ldc, int kc) {
  extern __shared__ char sm[];
  const uint32_t sb = smem_u32(sm);
  float* bias_s = (float*)(sm + FC_BIAS_OFF);
  const int tid = threadIdx.x;
  const int lane = tid & 31, wid = tid >> 5;
  const int wm = wid & 3, wn = wid >> 2;
  const int n0 = blockIdx.x * 128;
  const int m0 = blockIdx.y * 128;
  if (tid < 128) bias_s[tid] = bias ? bias[n0 + tid] : 0.f;

  const int lrow = tid >> 1;
  const int lhalf = tid & 1;

  float c[2][8][4];
#pragma unroll
  for (int i = 0; i < 2; i++)
#pragma unroll
    for (int j = 0; j < 8; j++)
#pragma unroll
      for (int q = 0; q < 4; q++) c[i][j][q] = 0.f;

  auto load_stage = [&](int kk, int buf) {
    const int k0 = kk * 64;
    const uint32_t base = sb + buf * FC_STAGE;
    const __nv_bfloat16* pa0 = Ahi + (size_t)(m0 + lrow) * lda + k0 + lhalf * 32;
    const __nv_bfloat16* pa1 = Alo + (size_t)(m0 + lrow) * lda + k0 + lhalf * 32;
    const __nv_bfloat16* pb0 = Bhi + (size_t)(n0 + lrow) * ldb + k0 + lhalf * 32;
    const __nv_bfloat16* pb1 = Blo + (size_t)(n0 + lrow) * ldb + k0 + lhalf * 32;
#pragma unroll
    for (int j = 0; j < 4; j++) {
      uint32_t o = SMEM_SWIZZLE_128B((uint32_t)(lrow * 128 + lhalf * 64 + j * 16));
      asm volatile("cp.async.cg.shared.global [%0], [%1], 16;"
                   :: "r"(base + FCS_AHI + o), "l"(pa0 + j * 8));
      asm volatile("cp.async.cg.shared.global [%0], [%1], 16;"
                   :: "r"(base + FCS_ALO + o), "l"(pa1 + j * 8));
      asm volatile("cp.async.cg.shared.global [%0], [%1], 16;"
                   :: "r"(base + FCS_BHI + o), "l"(pb0 + j * 8));
      asm volatile("cp.async.cg.shared.global [%0], [%1], 16;"
                   :: "r"(base + FCS_BLO + o), "l"(pb1 + j * 8));
    }
    asm volatile("cp.async.commit_group;");
  };

  auto ld_a = [&](uint32_t abase, int ks, uint32_t (*a)[4]) {
#pragma unroll
    for (int mt = 0; mt < 2; mt++) {
      uint32_t row = wm * 32 + mt * 16 + (lane & 15);
      uint32_t off = SMEM_SWIZZLE_128B(row * 128 + ks * 32 + (lane >> 4) * 16);
      asm volatile("ldmatrix.sync.aligned.m8n8.x4.shared.b16 {%0,%1,%2,%3}, [%4];"
                   : "=r"(a[mt][0]), "=r"(a[mt][1]), "=r"(a[mt][2]), "=r"(a[mt][3])
                   : "r"(abase + off));
    }
  };
  auto ld_b = [&](uint32_t bbase, int ks, uint32_t (*b)[4]) {
#pragma unroll
    for (int np = 0; np < 4; np++) {
      uint32_t row = wn * 64 + np * 16 + (lane & 7) + ((lane >> 4) & 1) * 8;
      uint32_t off = SMEM_SWIZZLE_128B(row * 128 + ks * 32 + ((lane >> 3) & 1) * 16);
      asm volatile("ldmatrix.sync.aligned.m8n8.x4.shared.b16 {%0,%1,%2,%3}, [%4];"
                   : "=r"(b[np][0]), "=r"(b[np][1]), "=r"(b[np][2]), "=r"(b[np][3])
                   : "r"(bbase + off));
    }
  };
  auto do_mma = [&](uint32_t (*a)[4], uint32_t (*b)[4]) {
#pragma unroll
    for (int mt = 0; mt < 2; mt++)
#pragma unroll
      for (int nt = 0; nt < 8; nt++) {
        asm volatile(
            "mma.sync.aligned.m16n8k16.row.col.f32.bf16.bf16.f32 "
            "{%0,%1,%2,%3}, {%4,%5,%6,%7}, {%8,%9}, {%0,%1,%2,%3};"
            : "+f"(c[mt][nt][0]), "+f"(c[mt][nt][1]),
              "+f"(c[mt][nt][2]), "+f"(c[mt][nt][3])
            : "r"(a[mt][0]), "r"(a[mt][1]), "r"(a[mt][2]), "r"(a[mt][3]),
              "r"(b[nt >> 1][(nt & 1) * 2]), "r"(b[nt >> 1][(nt & 1) * 2 + 1]));
      }
  };

  load_stage(0, 0);
  for (int it = 0; it < kc; it++) {
    asm volatile("cp.async.wait_group 0;");
    __syncthreads();
    if (it + 1 < kc) load_stage(it + 1, (it + 1) & 1);
    const uint32_t base = sb + (it & 1) * FC_STAGE;
#pragma unroll
    for (int ks = 0; ks < 4; ks++) {
      uint32_t a[2][4], b[4][4];
      ld_a(base + FCS_AHI, ks, a);
      ld_b(base + FCS_BHI, ks, b);
      do_mma(a, b);                 // Ahi * Bhi
      ld_a(base + FCS_ALO, ks, a);
      do_mma(a, b);                 // Alo * Bhi (B frags reused)
      ld_a(base + FCS_AHI, ks, a);
      ld_b(base + FCS_BLO, ks, b);
      do_mma(a, b);                 // Ahi * Blo
    }
    __syncthreads();
  }

  // epilogue: + bias (smem) and optional per-user P row (global, L2-resident)
#pragma unroll
  for (int mt = 0; mt < 2; mt++) {
    int r = m0 + wm * 32 + mt * 16 + (lane >> 2);
    const float* p0 = P ? (P + (size_t)(r & 127) * V_DIM + n0) : nullptr;
    const float* p1 = P ? (P + (size_t)((r + 8) & 127) * V_DIM + n0) : nullptr;
#pragma unroll
    for (int nt = 0; nt < 8; nt++) {
      int col = wn * 64 + nt * 8 + (lane & 3) * 2;
      float bx = bias_s[col], by = bias_s[col + 1];
      float2 v0 = {c[mt][nt][0] + bx, c[mt][nt][1] + by};
      float2 v1 = {c[mt][nt][2] + bx, c[mt][nt][3] + by};
      if (P) {
        float2 q0 = *(const float2*)(p0 + col);
        float2 q1 = *(const float2*)(p1 + col);
        v0.x += q0.x; v0.y += q0.y;
        v1.x += q1.x; v1.y += q1.y;
      }
      *(float2*)(C + (size_t)r * ldc + n0 + col) = v0;
      *(float2*)(C + (size_t)(r + 8) * ldc + n0 + col) = v1;
    }
  }
}

// ---------------------------------------------------------------------------
extern "C" void kernel_launch(void* const* d_in, const int* in_sizes, int n_in,
                              void* d_out, int out_size) {
  const int*   x    = (const int*)  d_in[0];
  const float* t    = (const float*)d_in[1];
  const float* sc   = (const float*)d_in[2];
  const float* h_in = (const float*)d_in[5];
  const int*   au   = (const int*)  d_in[6];
  const float* emb  = (const float*)d_in[7];
  const float* uemb = (const float*)d_in[8];
  const float* Wih  = (const float*)d_in[9];
  const float* Whh  = (const float*)d_in[10];
  const float* bih  = (const float*)d_in[11];
  const float* bhh  = (const float*)d_in[12];
  const float* fcW  = (const float*)d_in[13];
  const float* fcb  = (const float*)d_in[14];
  float* out = (float*)d_out;

  cudaFuncSetAttribute(rnn_persist, cudaFuncAttributeMaxDynamicSharedMemorySize, RNN_SMEM);
  cudaFuncSetAttribute(gemm3, cudaFuncAttributeMaxDynamicSharedMemorySize, FC_SMEM);

  __nv_bfloat16 *pAhi, *pAlo, *pWhi, *pWlo, *pXhi, *pXlo, *pWihHi, *pWihLo, *pPhi, *pPlo;
  float *pbias2, *pxw, *pP;
  cudaGetSymbolAddress((void**)&pAhi, g_Ahi);
  cudaGetSymbolAddress((void**)&pAlo, g_Alo);
  cudaGetSymbolAddress((void**)&pWhi, g_Whi);
  cudaGetSymbolAddress((void**)&pWlo, g_Wlo);
  cudaGetSymbolAddress((void**)&pXhi, g_Xhi);
  cudaGetSymbolAddress((void**)&pXlo, g_Xlo);
  cudaGetSymbolAddress((void**)&pWihHi, g_WihHi);
  cudaGetSymbolAddress((void**)&pWihLo, g_WihLo);
  cudaGetSymbolAddress((void**)&pPhi, g_Phi);
  cudaGetSymbolAddress((void**)&pPlo, g_Plo);
  cudaGetSymbolAddress((void**)&pbias2, g_bias2);
  cudaGetSymbolAddress((void**)&pxw, g_xw);
  cudaGetSymbolAddress((void**)&pP, g_P);

  // ---- fork a second stream for the preamble chain (capture-safe pattern)
  cudaStream_t s1;
  cudaStreamCreateWithFlags(&s1, cudaStreamNonBlocking);
  cudaEvent_t evFork, evWih, evFlash, evP;
  cudaEventCreateWithFlags(&evFork, cudaEventDisableTiming);
  cudaEventCreateWithFlags(&evWih, cudaEventDisableTiming);
  cudaEventCreateWithFlags(&evFlash, cudaEventDisableTiming);
  cudaEventCreateWithFlags(&evP, cudaEventDisableTiming);

  cudaEventRecord(evFork, 0);
  cudaStreamWaitEvent(s1, evFork, 0);

  // stream 1: p_u gather + bias2, Wih split, flashweights, fcW split, P-gemm
  pu_split<<<U_DIM, 128, 0, s1>>>(au, uemb, bih, bhh);
  wsplit<<<(H_DIM * H_DIM) / (256 * 4), 256, 0, s1>>>(Wih, pWihHi, pWihLo);
  cudaEventRecord(evWih, s1);            // bias2 + Wih split ready
  flashweights<<<dim3(128, 128), 128, 0, s1>>>(t, sc);
  cudaEventRecord(evFlash, s1);          // w + sumw ready
  wsplit<<<(V_DIM * K2_DIM) / (256 * 4), 256, 0, s1>>>(fcW, pWhi, pWlo);
  gemm3<<<dim3(64, 1), 256, FC_SMEM, s1>>>(pPhi, pPlo, pWhi + H_DIM, pWlo + H_DIM,
                                           fcb, nullptr, pP, H_DIM, K2_DIM, V_DIM, 8);
  cudaEventRecord(evP, s1);              // Whi/Wlo + P ready

  // stream 0: critical chain
  gather_split<<<M_DIM, 128>>>(x, emb);
  cudaStreamWaitEvent(0, evWih, 0);
  gemm3<<<dim3(4, 128), 256, FC_SMEM>>>(pXhi, pXlo, pWihHi, pWihLo,
                                        pbias2, nullptr, pxw, H_DIM, H_DIM, H_DIM, 8);
  rnn_persist<<<dim3(16, 8), 128, RNN_SMEM>>>(h_in, Whh, out + (size_t)M_DIM * V_DIM);
  cudaStreamWaitEvent(0, evFlash, 0);
  einsum_gemm<<<dim3(8, 4, 128), 128>>>();
  cudaStreamWaitEvent(0, evP, 0);
  gemm3<<<dim3(64, 128), 256, FC_SMEM>>>(pAhi, pAlo, pWhi, pWlo,
                                         nullptr, pP, out, H_DIM, K2_DIM, V_DIM, 8);

  cudaEventDestroy(evFork);
  cudaEventDestroy(evWih);
  cudaEventDestroy(evFlash);
  cudaEventDestroy(evP);
  cudaStreamDestroy(s1);
}

// round 13
// speedup vs baseline: 1.0664x; 1.0664x over previous
#include <cuda_runtime.h>
#include <cuda_bf16.h>
#include <cstdint>
#include <math.h>

#define S_DIM 128
#define U_DIM 128
#define H_DIM 512
#define V_DIM 8192
#define M_DIM (S_DIM * U_DIM)   /* 16384 */
#define K2_DIM (2 * H_DIM)      /* 1024  */

// ---------------- scratch (static device globals; no allocations) ----------
__device__ float g_xw[M_DIM * H_DIM];            // x_emb @ W_ih^T + biases
__device__ float g_out[M_DIM * H_DIM];           // RNN outputs
__device__ float g_w[U_DIM * S_DIM * S_DIM];     // flashback weights [u][i][j]
__device__ float g_sumw[U_DIM * S_DIM];
__device__ __nv_bfloat16 g_Ahi[(size_t)M_DIM * H_DIM];    // FC A hi (out_w only)
__device__ __nv_bfloat16 g_Alo[(size_t)M_DIM * H_DIM];    // FC A lo
__device__ __nv_bfloat16 g_Whi[(size_t)V_DIM * K2_DIM];   // FC W hi (full 1024)
__device__ __nv_bfloat16 g_Wlo[(size_t)V_DIM * K2_DIM];   // FC W lo
__device__ __nv_bfloat16 g_Xhi[(size_t)M_DIM * H_DIM];    // gathered x_emb hi
__device__ __nv_bfloat16 g_Xlo[(size_t)M_DIM * H_DIM];    // gathered x_emb lo
__device__ __nv_bfloat16 g_WihHi[H_DIM * H_DIM];
__device__ __nv_bfloat16 g_WihLo[H_DIM * H_DIM];
__device__ __nv_bfloat16 g_Phi[U_DIM * H_DIM];            // p_u hi
__device__ __nv_bfloat16 g_Plo[U_DIM * H_DIM];            // p_u lo
__device__ float g_P[(size_t)U_DIM * V_DIM];              // p_u @ W2^T + fc_b
__device__ float g_bias2[H_DIM];                          // b_ih + b_hh
__device__ unsigned g_bar_count;
__device__ unsigned g_bar_gen;

__device__ __forceinline__ uint32_t smem_u32(const void* p) {
  uint32_t a;
  asm("{ .reg .u64 t; cvta.to.shared.u64 t, %1; cvt.u32.u64 %0, t; }"
      : "=r"(a) : "l"(p));
  return a;
}
#define SMEM_SWIZZLE_128B(o) ((o) ^ (((o) >> 3) & 0x70))

// ---------------------------------------------------------------------------
// split helpers
// ---------------------------------------------------------------------------
__global__ __launch_bounds__(256) void wsplit(const float* __restrict__ w,
                                              __nv_bfloat16* __restrict__ hi,
                                              __nv_bfloat16* __restrict__ lo) {
  size_t i = ((size_t)blockIdx.x * 256 + threadIdx.x) * 4;
  float4 v = *(const float4*)(w + i);
  float vv[4] = {v.x, v.y, v.z, v.w};
#pragma unroll
  for (int j = 0; j < 4; j++) {
    __nv_bfloat16 h = __float2bfloat16(vv[j]);
    hi[i + j] = h;
    lo[i + j] = __float2bfloat16(vv[j] - __bfloat162float(h));
  }
}

__global__ __launch_bounds__(128) void gather_split(const int* __restrict__ x,
                                                    const float* __restrict__ emb) {
  const int m = blockIdx.x;
  const int tid = threadIdx.x;
  const int row = x[m];
  float4 v = *(const float4*)(emb + (size_t)row * H_DIM + tid * 4);
  float vv[4] = {v.x, v.y, v.z, v.w};
  size_t base = (size_t)m * H_DIM + tid * 4;
#pragma unroll
  for (int j = 0; j < 4; j++) {
    __nv_bfloat16 h = __float2bfloat16(vv[j]);
    g_Xhi[base + j] = h;
    g_Xlo[base + j] = __float2bfloat16(vv[j] - __bfloat162float(h));
  }
}

// gathers p_u, splits it, and (block 0) also builds b_ih+b_hh
__global__ __launch_bounds__(128) void pu_split(const int* __restrict__ au,
                                                const float* __restrict__ uemb,
                                                const float* __restrict__ bih,
                                                const float* __restrict__ bhh) {
  const int u = blockIdx.x;
  const int tid = threadIdx.x;
  if (u == 0) {
#pragma unroll
    for (int j = 0; j < 4; j++) {
      int i = tid * 4 + j;
      g_bias2[i] = bih[i] + bhh[i];
    }
  }
  float4 v = *(const float4*)(&uemb[(size_t)au[u] * H_DIM + tid * 4]);
  float vv[4] = {v.x, v.y, v.z, v.w};
  size_t base = (size_t)u * H_DIM + tid * 4;
#pragma unroll
  for (int j = 0; j < 4; j++) {
    __nv_bfloat16 h = __float2bfloat16(vv[j]);
    g_Phi[base + j] = h;
    g_Plo[base + j] = __float2bfloat16(vv[j] - __bfloat162float(h));
  }
}

// ---------------------------------------------------------------------------
// flashback weights + row sums (fast-math transcendentals)
// ---------------------------------------------------------------------------
__global__ __launch_bounds__(128) void flashweights(
    const float* __restrict__ t, const float* __restrict__ sc) {
  const int i = blockIdx.x, u = blockIdx.y;
  const int j = threadIdx.x;
  float w = 0.f;
  if (j <= i) {
    float ti = t[i * U_DIM + u], tj = t[j * U_DIM + u];
    float six = sc[(i * U_DIM + u) * 2 + 0], siy = sc[(i * U_DIM + u) * 2 + 1];
    float sjx = sc[(j * U_DIM + u) * 2 + 0], sjy = sc[(j * U_DIM + u) * 2 + 1];
    float dt = ti - tj;
    float dx = six - sjx, dy = siy - sjy;
    float ds = sqrtf(dx * dx + dy * dy);
    float a = (__cosf(dt * 7.2722052166430399e-05f) + 1.0f) * 0.5f *
              __expf(dt * (-0.1f / 86400.0f));
    float b = __expf(-100.0f * ds);
    w = a * b + 1e-10f;
  }
  g_w[((size_t)u * S_DIM + i) * S_DIM + j] = w;
  __shared__ float red[128];
  red[j] = w;
  __syncthreads();
#pragma unroll
  for (int st = 64; st > 0; st >>= 1) {
    if (j < st) red[j] += red[j + st];
    __syncthreads();
  }
  if (j == 0) g_sumw[u * S_DIM + i] = red[0];
}

// ---------------------------------------------------------------------------
// persistent RNN — R8 core; last step also writes h_out to the output tail
// ---------------------------------------------------------------------------
#define RNN_WS 34
#define RNN_HS 18
#define RNN_SMEM (512 * RNN_WS * 4 + 512 * RNN_HS * 4)
__global__ __launch_bounds__(128) void rnn_persist(const float* __restrict__ h_in,
                                                   const float* __restrict__ Whh,
                                                   float* __restrict__ hout_dst) {
  extern __shared__ float sf[];
  float* Ws = sf;
  float* Hs = sf + 512 * RNN_WS;
  const int tid = threadIdx.x;
  const int n0 = blockIdx.x * 32;
  const int u0base = blockIdx.y * 16;
  {
    int c = tid & 31, kg = tid >> 5;
    for (int k0 = 0; k0 < 512; k0 += 16) {
      int k = k0 + kg * 4;
      float4 v = *(const float4*)(Whh + (size_t)(n0 + c) * H_DIM + k);
      Ws[(k + 0) * RNN_WS + c] = v.x; Ws[(k + 1) * RNN_WS + c] = v.y;
      Ws[(k + 2) * RNN_WS + c] = v.z; Ws[(k + 3) * RNN_WS + c] = v.w;
    }
  }
  unsigned mygen = 0;
  if (tid == 0) mygen = *((volatile unsigned*)&g_bar_gen);
  __syncthreads();

  const int tx = tid & 15, ty = tid >> 4;
  for (int s = 0; s < S_DIM; s++) {
    const float* hp = (s == 0) ? h_in : (g_out + (size_t)(s - 1) * U_DIM * H_DIM);
    {
      int uu = tid >> 3, kg2 = tid & 7;
      const float* hrow = hp + (size_t)(u0base + uu) * H_DIM;
      for (int k0 = 0; k0 < 512; k0 += 32) {
        int k = k0 + kg2 * 4;
        float4 v = *(const float4*)(hrow + k);
        Hs[(k + 0) * RNN_HS + uu] = v.x; Hs[(k + 1) * RNN_HS + uu] = v.y;
        Hs[(k + 2) * RNN_HS + uu] = v.z; Hs[(k + 3) * RNN_HS + uu] = v.w;
      }
    }
    __syncthreads();
    float a00 = 0.f, a01 = 0.f, a10 = 0.f, a11 = 0.f;
#pragma unroll 8
    for (int k = 0; k < 512; k++) {
      float2 a = *(const float2*)(&Hs[k * RNN_HS + ty * 2]);
      float2 b = *(const float2*)(&Ws[k * RNN_WS + tx * 2]);
      a00 += a.x * b.x; a01 += a.x * b.y;
      a10 += a.y * b.x; a11 += a.y * b.y;
    }
    const float* xw = g_xw + (size_t)s * U_DIM * H_DIM;
    float* ho = g_out + (size_t)s * U_DIM * H_DIM;
    size_t o00 = (size_t)(u0base + ty * 2) * H_DIM + n0 + tx * 2;
    size_t o10 = o00 + H_DIM;
    float v00 = tanhf(a00 + xw[o00]);
    float v01 = tanhf(a01 + xw[o00 + 1]);
    float v10 = tanhf(a10 + xw[o10]);
    float v11 = tanhf(a11 + xw[o10 + 1]);
    ho[o00]     = v00;
    ho[o00 + 1] = v01;
    ho[o10]     = v10;
    ho[o10 + 1] = v11;
    if (s == S_DIM - 1) {
      hout_dst[o00]     = v00;
      hout_dst[o00 + 1] = v01;
      hout_dst[o10]     = v10;
      hout_dst[o10 + 1] = v11;
    }
    __syncthreads();
    if (tid == 0) {
      __threadfence();
      unsigned arr = atomicAdd(&g_bar_count, 1);
      if (arr == 127) {
        g_bar_count = 0;
        __threadfence();
        atomicAdd(&g_bar_gen, 1);
      } else {
        while (*((volatile unsigned*)&g_bar_gen) == mygen) { }
        __threadfence();
      }
      mygen++;
    }
    __syncthreads();
  }
}

// ---------------------------------------------------------------------------
// per-user einsum -> bf16 hi/lo of FC A (stride 512) — R8 exact
// ---------------------------------------------------------------------------
__global__ __launch_bounds__(128) void einsum_gemm() {
  __shared__ float As[16][32];
  __shared__ float Bs[16][64];
  const int nt = blockIdx.x, mt = blockIdx.y, u = blockIdx.z;
  const int tid = threadIdx.x;
  const int m0 = mt * 32, n0 = nt * 64;
  const int tx = tid & 15, ty = tid >> 4;
  float acc[4][4];
#pragma unroll
  for (int i = 0; i < 4; i++)
#pragma unroll
    for (int j = 0; j < 4; j++) acc[i][j] = 0.f;
  for (int k0 = 0; k0 < 128; k0 += 16) {
    {
      int row = tid >> 2, kq = (tid & 3) * 4;
      float4 v = *(const float4*)(&g_w[((size_t)u * S_DIM + m0 + row) * S_DIM + k0 + kq]);
      As[kq + 0][row] = v.x; As[kq + 1][row] = v.y;
      As[kq + 2][row] = v.z; As[kq + 3][row] = v.w;
    }
#pragma unroll
    for (int h2 = 0; h2 < 2; h2++) {
      int id = tid + h2 * 128;
      int jr = id >> 4, hq = (id & 15) * 4;
      float4 v = *(const float4*)(&g_out[((size_t)(k0 + jr) * U_DIM + u) * H_DIM + n0 + hq]);
      *(float4*)(&Bs[jr][hq]) = v;
    }
    __syncthreads();
#pragma unroll
    for (int k = 0; k < 16; k++) {
      float a[4], b[4];
      *(float4*)(&a[0]) = *(const float4*)(&As[k][ty * 4]);
      *(float4*)(&b[0]) = *(const float4*)(&Bs[k][tx * 4]);
#pragma unroll
      for (int i = 0; i < 4; i++)
#pragma unroll
        for (int j = 0; j < 4; j++) acc[i][j] += a[i] * b[j];
    }
    __syncthreads();
  }
#pragma unroll
  for (int r = 0; r < 4; r++) {
    int i = m0 + ty * 4 + r;
    float inv = 1.0f / g_sumw[u * S_DIM + i];
#pragma unroll
    for (int c = 0; c < 4; c++) {
      int h = n0 + tx * 4 + c;
      float v = acc[r][c] * inv;
      size_t idx = ((size_t)i * U_DIM + u) * H_DIM + h;
      __nv_bfloat16 hi = __float2bfloat16(v);
      g_Ahi[idx] = hi;
      g_Alo[idx] = __float2bfloat16(v - __bfloat162float(hi));
    }
  }
}

// ---------------------------------------------------------------------------
// 3-term bf16-split GEMM, fused-term stages (R11 exact)
// ---------------------------------------------------------------------------
#define FCS_AHI 0
#define FCS_ALO 16384
#define FCS_BHI 32768
#define FCS_BLO 49152
#define FC_STAGE 65536
#define FC_BIAS_OFF 131072
#define FC_SMEM 131584
__global__ __launch_bounds__(256) void gemm3(
    const __nv_bfloat16* __restrict__ Ahi, const __nv_bfloat16* __restrict__ Alo,
    const __nv_bfloat16* __restrict__ Bhi, const __nv_bfloat16* __restrict__ Blo,
    const float* __restrict__ bias, const float* __restrict__ P,
    float* __restrict__ C, int lda, int ldb, int ldc, int kc) {
  extern __shared__ char sm[];
  const uint32_t sb = smem_u32(sm);
  float* bias_s = (float*)(sm + FC_BIAS_OFF);
  const int tid = threadIdx.x;
  const int lane = tid & 31, wid = tid >> 5;
  const int wm = wid & 3, wn = wid >> 2;
  const int n0 = blockIdx.x * 128;
  const int m0 = blockIdx.y * 128;
  if (tid < 128) bias_s[tid] = bias ? bias[n0 + tid] : 0.f;

  const int lrow = tid >> 1;
  const int lhalf = tid & 1;

  float c[2][8][4];
#pragma unroll
  for (int i = 0; i < 2; i++)
#pragma unroll
    for (int j = 0; j < 8; j++)
#pragma unroll
      for (int q = 0; q < 4; q++) c[i][j][q] = 0.f;

  auto load_stage = [&](int kk, int buf) {
    const int k0 = kk * 64;
    const uint32_t base = sb + buf * FC_STAGE;
    const __nv_bfloat16* pa0 = Ahi + (size_t)(m0 + lrow) * lda + k0 + lhalf * 32;
    const __nv_bfloat16* pa1 = Alo + (size_t)(m0 + lrow) * lda + k0 + lhalf * 32;
    const __nv_bfloat16* pb0 = Bhi + (size_t)(n0 + lrow) * ldb + k0 + lhalf * 32;
    const __nv_bfloat16* pb1 = Blo + (size_t)(n0 + lrow) * ldb + k0 + lhalf * 32;
#pragma unroll
    for (int j = 0; j < 4; j++) {
      uint32_t o = SMEM_SWIZZLE_128B((uint32_t)(lrow * 128 + lhalf * 64 + j * 16));
      asm volatile("cp.async.cg.shared.global [%0], [%1], 16;"
                   :: "r"(base + FCS_AHI + o), "l"(pa0 + j * 8));
      asm volatile("cp.async.cg.shared.global [%0], [%1], 16;"
                   :: "r"(base + FCS_ALO + o), "l"(pa1 + j * 8));
      asm volatile("cp.async.cg.shared.global [%0], [%1], 16;"
                   :: "r"(base + FCS_BHI + o), "l"(pb0 + j * 8));
      asm volatile("cp.async.cg.shared.global [%0], [%1], 16;"
                   :: "r"(base + FCS_BLO + o), "l"(pb1 + j * 8));
    }
    asm volatile("cp.async.commit_group;");
  };

  auto ld_a = [&](uint32_t abase, int ks, uint32_t (*a)[4]) {
#pragma unroll
    for (int mt = 0; mt < 2; mt++) {
      uint32_t row = wm * 32 + mt * 16 + (lane & 15);
      uint32_t off = SMEM_SWIZZLE_128B(row * 128 + ks * 32 + (lane >> 4) * 16);
      asm volatile("ldmatrix.sync.aligned.m8n8.x4.shared.b16 {%0,%1,%2,%3}, [%4];"
                   : "=r"(a[mt][0]), "=r"(a[mt][1]), "=r"(a[mt][2]), "=r"(a[mt][3])
                   : "r"(abase + off));
    }
  };
  auto ld_b = [&](uint32_t bbase, int ks, uint32_t (*b)[4]) {
#pragma unroll
    for (int np = 0; np < 4; np++) {
      uint32_t row = wn * 64 + np * 16 + (lane & 7) + ((lane >> 4) & 1) * 8;
      uint32_t off = SMEM_SWIZZLE_128B(row * 128 + ks * 32 + ((lane >> 3) & 1) * 16);
      asm volatile("ldmatrix.sync.aligned.m8n8.x4.shared.b16 {%0,%1,%2,%3}, [%4];"
                   : "=r"(b[np][0]), "=r"(b[np][1]), "=r"(b[np][2]), "=r"(b[np][3])
                   : "r"(bbase + off));
    }
  };
  auto do_mma = [&](uint32_t (*a)[4], uint32_t (*b)[4]) {
#pragma unroll
    for (int mt = 0; mt < 2; mt++)
#pragma unroll
      for (int nt = 0; nt < 8; nt++) {
        asm volatile(
            "mma.sync.aligned.m16n8k16.row.col.f32.bf16.bf16.f32 "
            "{%0,%1,%2,%3}, {%4,%5,%6,%7}, {%8,%9}, {%0,%1,%2,%3};"
            : "+f"(c[mt][nt][0]), "+f"(c[mt][nt][1]),
              "+f"(c[mt][nt][2]), "+f"(c[mt][nt][3])
            : "r"(a[mt][0]), "r"(a[mt][1]), "r"(a[mt][2]), "r"(a[mt][3]),
              "r"(b[nt >> 1][(nt & 1) * 2]), "r"(b[nt >> 1][(nt & 1) * 2 + 1]));
      }
  };

  load_stage(0, 0);
  for (int it = 0; it < kc; it++) {
    asm volatile("cp.async.wait_group 0;");
    __syncthreads();
    if (it + 1 < kc) load_stage(it + 1, (it + 1) & 1);
    const uint32_t base = sb + (it & 1) * FC_STAGE;
#pragma unroll
    for (int ks = 0; ks < 4; ks++) {
      uint32_t a[2][4], b[4][4];
      ld_a(base + FCS_AHI, ks, a);
      ld_b(base + FCS_BHI, ks, b);
      do_mma(a, b);                 // Ahi * Bhi
      ld_a(base + FCS_ALO, ks, a);
      do_mma(a, b);                 // Alo * Bhi (B frags reused)
      ld_a(base + FCS_AHI, ks, a);
      ld_b(base + FCS_BLO, ks, b);
      do_mma(a, b);                 // Ahi * Blo
    }
    __syncthreads();
  }

  // epilogue: + bias (smem) and optional per-user P row (global, L2-resident)
#pragma unroll
  for (int mt = 0; mt < 2; mt++) {
    int r = m0 + wm * 32 + mt * 16 + (lane >> 2);
    const float* p0 = P ? (P + (size_t)(r & 127) * V_DIM + n0) : nullptr;
    const float* p1 = P ? (P + (size_t)((r + 8) & 127) * V_DIM + n0) : nullptr;
#pragma unroll
    for (int nt = 0; nt < 8; nt++) {
      int col = wn * 64 + nt * 8 + (lane & 3) * 2;
      float bx = bias_s[col], by = bias_s[col + 1];
      float2 v0 = {c[mt][nt][0] + bx, c[mt][nt][1] + by};
      float2 v1 = {c[mt][nt][2] + bx, c[mt][nt][3] + by};
      if (P) {
        float2 q0 = *(const float2*)(p0 + col);
        float2 q1 = *(const float2*)(p1 + col);
        v0.x += q0.x; v0.y += q0.y;
        v1.x += q1.x; v1.y += q1.y;
      }
      *(float2*)(C + (size_t)r * ldc + n0 + col) = v0;
      *(float2*)(C + (size_t)(r + 8) * ldc + n0 + col) = v1;
    }
  }
}

// ---------------------------------------------------------------------------
extern "C" void kernel_launch(void* const* d_in, const int* in_sizes, int n_in,
                              void* d_out, int out_size) {
  const int*   x    = (const int*)  d_in[0];
  const float* t    = (const float*)d_in[1];
  const float* sc   = (const float*)d_in[2];
  const float* h_in = (const float*)d_in[5];
  const int*   au   = (const int*)  d_in[6];
  const float* emb  = (const float*)d_in[7];
  const float* uemb = (const float*)d_in[8];
  const float* Wih  = (const float*)d_in[9];
  const float* Whh  = (const float*)d_in[10];
  const float* bih  = (const float*)d_in[11];
  const float* bhh  = (const float*)d_in[12];
  const float* fcW  = (const float*)d_in[13];
  const float* fcb  = (const float*)d_in[14];
  float* out = (float*)d_out;

  cudaFuncSetAttribute(rnn_persist, cudaFuncAttributeMaxDynamicSharedMemorySize, RNN_SMEM);
  cudaFuncSetAttribute(gemm3, cudaFuncAttributeMaxDynamicSharedMemorySize, FC_SMEM);

  __nv_bfloat16 *pAhi, *pAlo, *pWhi, *pWlo, *pXhi, *pXlo, *pWihHi, *pWihLo, *pPhi, *pPlo;
  float *pbias2, *pxw, *pP;
  cudaGetSymbolAddress((void**)&pAhi, g_Ahi);
  cudaGetSymbolAddress((void**)&pAlo, g_Alo);
  cudaGetSymbolAddress((void**)&pWhi, g_Whi);
  cudaGetSymbolAddress((void**)&pWlo, g_Wlo);
  cudaGetSymbolAddress((void**)&pXhi, g_Xhi);
  cudaGetSymbolAddress((void**)&pXlo, g_Xlo);
  cudaGetSymbolAddress((void**)&pWihHi, g_WihHi);
  cudaGetSymbolAddress((void**)&pWihLo, g_WihLo);
  cudaGetSymbolAddress((void**)&pPhi, g_Phi);
  cudaGetSymbolAddress((void**)&pPlo, g_Plo);
  cudaGetSymbolAddress((void**)&pbias2, g_bias2);
  cudaGetSymbolAddress((void**)&pxw, g_xw);
  cudaGetSymbolAddress((void**)&pP, g_P);

  // ---- fork a second stream (capture-safe event pattern)
  cudaStream_t s1;
  cudaStreamCreateWithFlags(&s1, cudaStreamNonBlocking);
  cudaEvent_t evFork, evWih, evFlash, evRnn, evP;
  cudaEventCreateWithFlags(&evFork, cudaEventDisableTiming);
  cudaEventCreateWithFlags(&evWih, cudaEventDisableTiming);
  cudaEventCreateWithFlags(&evFlash, cudaEventDisableTiming);
  cudaEventCreateWithFlags(&evRnn, cudaEventDisableTiming);
  cudaEventCreateWithFlags(&evP, cudaEventDisableTiming);

  cudaEventRecord(evFork, 0);
  cudaStreamWaitEvent(s1, evFork, 0);

  // s1 (pre-RNN, small kernels only): p_u/bias2, Wih split, flashweights
  pu_split<<<U_DIM, 128, 0, s1>>>(au, uemb, bih, bhh);
  wsplit<<<(H_DIM * H_DIM) / (256 * 4), 256, 0, s1>>>(Wih, pWihHi, pWihLo);
  cudaEventRecord(evWih, s1);
  flashweights<<<dim3(128, 128), 128, 0, s1>>>(t, sc);
  cudaEventRecord(evFlash, s1);

  // stream 0: critical chain
  gather_split<<<M_DIM, 128>>>(x, emb);
  cudaStreamWaitEvent(0, evWih, 0);
  gemm3<<<dim3(4, 128), 256, FC_SMEM>>>(pXhi, pXlo, pWihHi, pWihLo,
                                        pbias2, nullptr, pxw, H_DIM, H_DIM, H_DIM, 8);
  rnn_persist<<<dim3(16, 8), 128, RNN_SMEM>>>(h_in, Whh, out + (size_t)M_DIM * V_DIM);
  cudaEventRecord(evRnn, 0);

  // s1 (post-RNN, overlaps einsum): fcW split + P-gemm
  cudaStreamWaitEvent(s1, evRnn, 0);
  wsplit<<<(V_DIM * K2_DIM) / (256 * 4), 256, 0, s1>>>(fcW, pWhi, pWlo);
  gemm3<<<dim3(64, 1), 256, FC_SMEM, s1>>>(pPhi, pPlo, pWhi + H_DIM, pWlo + H_DIM,
                                           fcb, nullptr, pP, H_DIM, K2_DIM, V_DIM, 8);
  cudaEventRecord(evP, s1);

  // stream 0: einsum (overlaps s1's P chain), then FC
  cudaStreamWaitEvent(0, evFlash, 0);
  einsum_gemm<<<dim3(8, 4, 128), 128>>>();
  cudaStreamWaitEvent(0, evP, 0);
  gemm3<<<dim3(64, 128), 256, FC_SMEM>>>(pAhi, pAlo, pWhi, pWlo,
                                         nullptr, pP, out, H_DIM, K2_DIM, V_DIM, 8);

  cudaEventDestroy(evFork);
  cudaEventDestroy(evWih);
  cudaEventDestroy(evFlash);
  cudaEventDestroy(evRnn);
  cudaEventDestroy(evP);
  cudaStreamDestroy(s1);
}